// round 2
// baseline (speedup 1.0000x reference)
#include <cuda_runtime.h>

#define MAXN 20000
#define DIN  128
#define DHID 256
#define DDNS 128

// Persistent scratch. Accumulators (g_de, g_se, g_te, g_y, g_sum_s) are zero
// at module load and re-zeroed by each run AFTER their last consumption, so
// every replay (and the first correctness run) sees clean state.
__device__ float g_de  [MAXN];   // edge-accumulated degree (without self-loop)
__device__ float g_dinv[MAXN];
__device__ float g_s   [MAXN];
__device__ float g_q   [MAXN];   // dinv * s
__device__ float g_se  [MAXN];   // edge part of s
__device__ float g_te  [MAXN];   // edge part of t
__device__ float g_y   [DIN];
__device__ float g_sum_s;

// ---------------------------------------------------------------------------
// Edge pass 1: deg_edge[c] += w    (4 edges per thread)
__global__ void k_deg(const int* __restrict__ col, const float* __restrict__ w, int e) {
    int i = blockIdx.x * blockDim.x + threadIdx.x;
    int b = i * 4;
    if (b + 3 < e) {
        int4   c4 = *(const int4*)  (col + b);
        float4 w4 = *(const float4*)(w   + b);
        atomicAdd(&g_de[c4.x], w4.x);
        atomicAdd(&g_de[c4.y], w4.y);
        atomicAdd(&g_de[c4.z], w4.z);
        atomicAdd(&g_de[c4.w], w4.w);
    } else if (b < e) {
        for (int k = b; k < e; k++) atomicAdd(&g_de[col[k]], w[k]);
    }
}

// Node pass 1: dinv = rsqrt(1 + deg_edge)   (self-loop weight 1)
__global__ void k_node1(int n) {
    int i = blockIdx.x * blockDim.x + threadIdx.x;
    if (i < n) g_dinv[i] = rsqrtf(1.0f + g_de[i]);
}

// Edge pass 2: s_edge[r] += w * dinv[c]   (single gather per edge)
__global__ void k_s(const int* __restrict__ row, const int* __restrict__ col,
                    const float* __restrict__ w, int e) {
    int i = blockIdx.x * blockDim.x + threadIdx.x;
    int b = i * 4;
    if (b + 3 < e) {
        int4   r4 = *(const int4*)  (row + b);
        int4   c4 = *(const int4*)  (col + b);
        float4 w4 = *(const float4*)(w   + b);
        float p0 = w4.x * __ldg(&g_dinv[c4.x]);
        float p1 = w4.y * __ldg(&g_dinv[c4.y]);
        float p2 = w4.z * __ldg(&g_dinv[c4.z]);
        float p3 = w4.w * __ldg(&g_dinv[c4.w]);
        atomicAdd(&g_se[r4.x], p0);
        atomicAdd(&g_se[r4.y], p1);
        atomicAdd(&g_se[r4.z], p2);
        atomicAdd(&g_se[r4.w], p3);
    } else if (b < e) {
        for (int k = b; k < e; k++)
            atomicAdd(&g_se[row[k]], w[k] * __ldg(&g_dinv[col[k]]));
    }
}

// Node pass 2: s = dinv*s_edge + dinv^2 ; q = dinv*s ; sum_s ; re-zero de/se
__global__ void k_node2(int n) {
    int i = blockIdx.x * blockDim.x + threadIdx.x;
    float sv = 0.0f;
    if (i < n) {
        float di = g_dinv[i];
        float s  = di * g_se[i] + di * di;
        g_s[i] = s;
        g_q[i] = di * s;
        g_se[i] = 0.0f;   // clean for next run
        g_de[i] = 0.0f;   // clean for next run
        sv = s;
    }
    #pragma unroll
    for (int o = 16; o > 0; o >>= 1) sv += __shfl_down_sync(0xffffffffu, sv, o);
    __shared__ float ws[8];
    int lane = threadIdx.x & 31, wid = threadIdx.x >> 5;
    if (lane == 0) ws[wid] = sv;
    __syncthreads();
    if (wid == 0) {
        sv = (lane < (blockDim.x >> 5)) ? ws[lane] : 0.0f;
        #pragma unroll
        for (int o = 4; o > 0; o >>= 1) sv += __shfl_down_sync(0xffffffffu, sv, o);
        if (lane == 0) atomicAdd(&g_sum_s, sv);
    }
}

// Edge pass 3: t_edge[r] += w * q[c]
__global__ void k_t(const int* __restrict__ row, const int* __restrict__ col,
                    const float* __restrict__ w, int e) {
    int i = blockIdx.x * blockDim.x + threadIdx.x;
    int b = i * 4;
    if (b + 3 < e) {
        int4   r4 = *(const int4*)  (row + b);
        int4   c4 = *(const int4*)  (col + b);
        float4 w4 = *(const float4*)(w   + b);
        float p0 = w4.x * __ldg(&g_q[c4.x]);
        float p1 = w4.y * __ldg(&g_q[c4.y]);
        float p2 = w4.z * __ldg(&g_q[c4.z]);
        float p3 = w4.w * __ldg(&g_q[c4.w]);
        atomicAdd(&g_te[r4.x], p0);
        atomicAdd(&g_te[r4.y], p1);
        atomicAdd(&g_te[r4.z], p2);
        atomicAdd(&g_te[r4.w], p3);
    } else if (b < e) {
        for (int k = b; k < e; k++)
            atomicAdd(&g_te[row[k]], w[k] * __ldg(&g_q[col[k]]));
    }
}

// y[d] = sum_n t[n] * X[n,d], with t[n] = dinv[n]*t_edge[n] + dinv[n]^2*s[n].
// Warp-per-row, float4 per lane (32 lanes * 16B = one 512B row).
// Also re-zeroes t_edge after its (only) read.
__global__ void k_y(const float* __restrict__ X, int n) {
    int tid  = threadIdx.x;
    int lane = tid & 31;
    int wid  = tid >> 5;                       // 8 warps
    int chunk = (n + gridDim.x - 1) / gridDim.x;
    int start = blockIdx.x * chunk;
    int end   = min(n, start + chunk);

    float4 acc = make_float4(0.f, 0.f, 0.f, 0.f);
    for (int r = start + wid; r < end; r += 8) {
        float te = g_te[r];
        float di = g_dinv[r];
        float sv = g_s[r];
        float tv = di * te + di * di * sv;
        if (lane == 0) g_te[r] = 0.0f;         // clean for next run
        float4 x = __ldg((const float4*)(X + (size_t)r * DIN) + lane);
        acc.x += tv * x.x;
        acc.y += tv * x.y;
        acc.z += tv * x.z;
        acc.w += tv * x.w;
    }

    __shared__ float sacc[8][DIN];
    sacc[wid][lane * 4 + 0] = acc.x;
    sacc[wid][lane * 4 + 1] = acc.y;
    sacc[wid][lane * 4 + 2] = acc.z;
    sacc[wid][lane * 4 + 3] = acc.w;
    __syncthreads();
    if (tid < DIN) {
        float v = 0.0f;
        #pragma unroll
        for (int k = 0; k < 8; k++) v += sacc[k][tid];
        atomicAdd(&g_y[tid], v);
    }
}

// Tail: u = y*W1 + sum_s*b1 ; g = u*W2/N + b2 ; z = relu(g*Wd1+bd1) ;
// logits = z*Wd2 + bd2 ; softmax. Then re-zero g_y / g_sum_s for next run.
__global__ void k_final(const float* __restrict__ W1, const float* __restrict__ b1,
                        const float* __restrict__ W2, const float* __restrict__ b2,
                        const float* __restrict__ Wd1, const float* __restrict__ bd1,
                        const float* __restrict__ Wd2, const float* __restrict__ bd2,
                        float* __restrict__ out, int n) {
    __shared__ float sy[DIN];
    __shared__ float su[DHID];
    __shared__ float sg[DHID];
    __shared__ float sz[DDNS];
    __shared__ float sl[2];
    int tid = threadIdx.x;

    float ss = g_sum_s;
    if (tid < DIN) sy[tid] = g_y[tid];
    __syncthreads();

    float accu = ss * b1[tid];
    #pragma unroll 8
    for (int d = 0; d < DIN; d++) accu += sy[d] * W1[d * DHID + tid];
    su[tid] = accu;
    __syncthreads();

    float accg = 0.0f;
    #pragma unroll 8
    for (int k = 0; k < DHID; k++) accg += su[k] * W2[k * DHID + tid];
    sg[tid] = accg / (float)n + b2[tid];
    __syncthreads();

    if (tid < DDNS) {
        float a = bd1[tid];
        #pragma unroll 8
        for (int j = 0; j < DHID; j++) a += sg[j] * Wd1[j * DDNS + tid];
        sz[tid] = a > 0.0f ? a : 0.0f;
    }
    __syncthreads();

    if (tid < 2) {
        float a = bd2[tid];
        for (int i = 0; i < DDNS; i++) a += sz[i] * Wd2[i * 2 + tid];
        sl[tid] = a;
    }
    __syncthreads();

    if (tid == 0) {
        float m  = fmaxf(sl[0], sl[1]);
        float e0 = __expf(sl[0] - m);
        float e1 = __expf(sl[1] - m);
        float inv = 1.0f / (e0 + e1);
        out[0] = e0 * inv;
        out[1] = e1 * inv;
        g_sum_s = 0.0f;                        // clean for next run
    }
    if (tid < DIN) g_y[tid] = 0.0f;            // clean for next run
}

// ---------------------------------------------------------------------------
extern "C" void kernel_launch(void* const* d_in, const int* in_sizes, int n_in,
                              void* d_out, int out_size) {
    const float* X   = (const float*)d_in[0];
    const int*   ei  = (const int*)  d_in[1];
    const float* w   = (const float*)d_in[2];
    const float* W1  = (const float*)d_in[3];
    const float* b1  = (const float*)d_in[4];
    const float* W2  = (const float*)d_in[5];
    const float* b2  = (const float*)d_in[6];
    const float* Wd1 = (const float*)d_in[7];
    const float* bd1 = (const float*)d_in[8];
    const float* Wd2 = (const float*)d_in[9];
    const float* bd2 = (const float*)d_in[10];
    float* out = (float*)d_out;

    int n = in_sizes[0] / DIN;        // 20000
    int e = in_sizes[2];              // 640000
    const int* row = ei;
    const int* col = ei + e;

    int nb_n  = (n + 255) / 256;
    int e4    = (e + 3) / 4;          // threads for vectorized edge passes
    int nb_e4 = (e4 + 255) / 256;

    k_deg  <<<nb_e4, 256>>>(col, w, e);
    k_node1<<<nb_n,  256>>>(n);
    k_s    <<<nb_e4, 256>>>(row, col, w, e);
    k_node2<<<nb_n,  256>>>(n);
    k_t    <<<nb_e4, 256>>>(row, col, w, e);
    k_y    <<<148,   256>>>(X, n);
    k_final<<<1,     256>>>(W1, b1, W2, b2, Wd1, bd1, Wd2, bd2, out, n);
}

// round 3
// speedup vs baseline: 1.1077x; 1.1077x over previous
#include <cuda_runtime.h>

#define MAXN 20000
#define DIN  128
#define DHID 256
#define DDNS 128

// Persistent scratch. All accumulators are zero at module load and re-zeroed
// by each run AFTER their last consumption, so every replay sees clean state.
__device__ float  g_de  [MAXN];   // edge-accumulated degree (no self-loop)
__device__ float  g_se  [MAXN];   // edge part of s
__device__ float  g_te  [MAXN];   // edge part of t
__device__ float  g_q   [MAXN];   // dinv * s (gathered in k_t)
__device__ float2 g_coef[MAXN];   // (di^2 * s, di)  for k_y: t = c.y*te + c.x
__device__ float  g_y   [DIN];
__device__ float  g_sum_s;

// ---------------------------------------------------------------------------
// Edge pass 1: de[c] += w     (scalar, 1 edge/thread — proven shape)
__global__ void k_deg(const int* __restrict__ col, const float* __restrict__ w, int e) {
    int i = blockIdx.x * blockDim.x + threadIdx.x;
    if (i < e) atomicAdd(&g_de[col[i]], w[i]);
}

// Edge pass 2 (fused node pass 1): se[r] += w * rsqrt(1 + de[c])
__global__ void k_s(const int* __restrict__ row, const int* __restrict__ col,
                    const float* __restrict__ w, int e) {
    int i = blockIdx.x * blockDim.x + threadIdx.x;
    if (i < e) {
        float de = __ldg(&g_de[col[i]]);
        atomicAdd(&g_se[row[i]], w[i] * rsqrtf(1.0f + de));
    }
}

// Node pass: di = rsqrt(1+de); s = di*se + di^2; q = di*s;
// coef = (di^2*s, di); sum_s reduction; re-zero de/se for next run.
__global__ void k_node(int n) {
    int i = blockIdx.x * blockDim.x + threadIdx.x;
    float sv = 0.0f;
    if (i < n) {
        float di = rsqrtf(1.0f + g_de[i]);
        float s  = di * g_se[i] + di * di;
        g_q[i]    = di * s;
        g_coef[i] = make_float2(di * di * s, di);
        g_de[i] = 0.0f;
        g_se[i] = 0.0f;
        sv = s;
    }
    #pragma unroll
    for (int o = 16; o > 0; o >>= 1) sv += __shfl_down_sync(0xffffffffu, sv, o);
    __shared__ float ws[8];
    int lane = threadIdx.x & 31, wid = threadIdx.x >> 5;
    if (lane == 0) ws[wid] = sv;
    __syncthreads();
    if (wid == 0) {
        sv = (lane < (blockDim.x >> 5)) ? ws[lane] : 0.0f;
        #pragma unroll
        for (int o = 4; o > 0; o >>= 1) sv += __shfl_down_sync(0xffffffffu, sv, o);
        if (lane == 0) atomicAdd(&g_sum_s, sv);
    }
}

// Edge pass 3: te[r] += w * q[c]
__global__ void k_t(const int* __restrict__ row, const int* __restrict__ col,
                    const float* __restrict__ w, int e) {
    int i = blockIdx.x * blockDim.x + threadIdx.x;
    if (i < e) {
        float q = __ldg(&g_q[col[i]]);
        atomicAdd(&g_te[row[i]], w[i] * q);
    }
}

// y[d] = sum_n t[n] * X[n,d] with t[n] = coef.y*te[n] + coef.x.
// Warp-per-row, float4 per lane (32 lanes * 16B = one 512B row).
// Re-zeroes te after its only read.
__global__ void k_y(const float* __restrict__ X, int n) {
    int tid  = threadIdx.x;
    int lane = tid & 31;
    int wid  = tid >> 5;                       // 8 warps
    int chunk = (n + gridDim.x - 1) / gridDim.x;
    int start = blockIdx.x * chunk;
    int end   = min(n, start + chunk);

    float4 acc = make_float4(0.f, 0.f, 0.f, 0.f);
    for (int r = start + wid; r < end; r += 8) {
        float2 c  = g_coef[r];
        float  te = g_te[r];
        float  tv = c.y * te + c.x;
        if (lane == 0) g_te[r] = 0.0f;         // clean for next run
        float4 x = __ldg((const float4*)(X + (size_t)r * DIN) + lane);
        acc.x += tv * x.x;
        acc.y += tv * x.y;
        acc.z += tv * x.z;
        acc.w += tv * x.w;
    }

    __shared__ float sacc[8][DIN];
    sacc[wid][lane * 4 + 0] = acc.x;
    sacc[wid][lane * 4 + 1] = acc.y;
    sacc[wid][lane * 4 + 2] = acc.z;
    sacc[wid][lane * 4 + 3] = acc.w;
    __syncthreads();
    if (tid < DIN) {
        float v = 0.0f;
        #pragma unroll
        for (int k = 0; k < 8; k++) v += sacc[k][tid];
        atomicAdd(&g_y[tid], v);
    }
}

// Tail: u = y*W1 + sum_s*b1 ; g = u*W2/N + b2 ; z = relu(g*Wd1+bd1) ;
// logits = z*Wd2 + bd2 ; softmax. Re-zero g_y / g_sum_s for next run.
__global__ void k_final(const float* __restrict__ W1, const float* __restrict__ b1,
                        const float* __restrict__ W2, const float* __restrict__ b2,
                        const float* __restrict__ Wd1, const float* __restrict__ bd1,
                        const float* __restrict__ Wd2, const float* __restrict__ bd2,
                        float* __restrict__ out, int n) {
    __shared__ float sy[DIN];
    __shared__ float su[DHID];
    __shared__ float sg[DHID];
    __shared__ float sz[DDNS];
    __shared__ float sl[2];
    int tid = threadIdx.x;

    float ss = g_sum_s;
    if (tid < DIN) sy[tid] = g_y[tid];
    __syncthreads();

    float accu = ss * b1[tid];
    #pragma unroll 8
    for (int d = 0; d < DIN; d++) accu += sy[d] * W1[d * DHID + tid];
    su[tid] = accu;
    __syncthreads();

    float accg = 0.0f;
    #pragma unroll 8
    for (int k = 0; k < DHID; k++) accg += su[k] * W2[k * DHID + tid];
    sg[tid] = accg / (float)n + b2[tid];
    __syncthreads();

    if (tid < DDNS) {
        float a = bd1[tid];
        #pragma unroll 8
        for (int j = 0; j < DHID; j++) a += sg[j] * Wd1[j * DDNS + tid];
        sz[tid] = a > 0.0f ? a : 0.0f;
    }
    __syncthreads();

    if (tid < 2) {
        float a = bd2[tid];
        for (int i = 0; i < DDNS; i++) a += sz[i] * Wd2[i * 2 + tid];
        sl[tid] = a;
    }
    __syncthreads();

    if (tid == 0) {
        float m  = fmaxf(sl[0], sl[1]);
        float e0 = __expf(sl[0] - m);
        float e1 = __expf(sl[1] - m);
        float inv = 1.0f / (e0 + e1);
        out[0] = e0 * inv;
        out[1] = e1 * inv;
        g_sum_s = 0.0f;
    }
    if (tid < DIN) g_y[tid] = 0.0f;
}

// ---------------------------------------------------------------------------
extern "C" void kernel_launch(void* const* d_in, const int* in_sizes, int n_in,
                              void* d_out, int out_size) {
    const float* X   = (const float*)d_in[0];
    const int*   ei  = (const int*)  d_in[1];
    const float* w   = (const float*)d_in[2];
    const float* W1  = (const float*)d_in[3];
    const float* b1  = (const float*)d_in[4];
    const float* W2  = (const float*)d_in[5];
    const float* b2  = (const float*)d_in[6];
    const float* Wd1 = (const float*)d_in[7];
    const float* bd1 = (const float*)d_in[8];
    const float* Wd2 = (const float*)d_in[9];
    const float* bd2 = (const float*)d_in[10];
    float* out = (float*)d_out;

    int n = in_sizes[0] / DIN;        // 20000
    int e = in_sizes[2];              // 640000
    const int* row = ei;
    const int* col = ei + e;

    int nb_n = (n + 255) / 256;
    int nb_e = (e + 255) / 256;       // 2500 blocks — proven edge shape

    k_deg  <<<nb_e, 256>>>(col, w, e);
    k_s    <<<nb_e, 256>>>(row, col, w, e);
    k_node <<<nb_n, 256>>>(n);
    k_t    <<<nb_e, 256>>>(row, col, w, e);
    k_y    <<<148,  256>>>(X, n);
    k_final<<<1,    256>>>(W1, b1, W2, b2, Wd1, bd1, Wd2, bd2, out, n);
}